// round 3
// baseline (speedup 1.0000x reference)
#include <cuda_runtime.h>
#include <math.h>

#define NIMG 512
#define NCLS 100000

// ---------------- scratch (device globals; no allocation) ----------------
__device__ float g_y1[512 * 16 * 56 * 56];   // conv1 out / act1
__device__ float g_y2[512 * 32 * 28 * 28];   // conv2 out / act2
__device__ float g_y3[512 * 64 * 26 * 26];   // conv3 out / act3
__device__ float g_y4[512 * 128 * 24 * 24];  // conv4 out / act4
__device__ float g_f[512 * 128];
__device__ float g_fn[512 * 128];
__device__ float g_wn[NCLS * 128];
__device__ float g_s1[16], g_q1[16];
__device__ float g_s2[32], g_q2[32];
__device__ float g_s3[64], g_q3[64];
__device__ float g_s4[128], g_q4[128];

// ---------------- stats zeroing ----------------
__global__ void zero_stats_k() {
    int t = threadIdx.x;
    if (t < 16)  { g_s1[t] = 0.f; g_q1[t] = 0.f; }
    if (t < 32)  { g_s2[t] = 0.f; g_q2[t] = 0.f; }
    if (t < 64)  { g_s3[t] = 0.f; g_q3[t] = 0.f; }
    if (t < 128) { g_s4[t] = 0.f; g_q4[t] = 0.f; }
}

// ---------------- conv1: 1->16, 4x4, stride 2, pad 1, 112 -> 56 ----------------
__global__ __launch_bounds__(256) void conv1_k(const float* __restrict__ x,
                                               const float* __restrict__ w) {
    __shared__ float ws[256];  // [tap][oc]
    int tid = threadIdx.x;
    // w layout OIHW: w[oc*16 + tap]; store transposed ws[tap*16 + oc]
    ws[(tid & 15) * 16 + (tid >> 4)] = w[tid];
    __syncthreads();
    int n = blockIdx.x;
    int p = blockIdx.y * 256 + tid;
    if (p >= 56 * 56) return;
    int oh = p / 56, ow = p % 56;
    const float* xin = x + (size_t)n * 112 * 112;
    float acc[16];
#pragma unroll
    for (int i = 0; i < 16; i++) acc[i] = 0.f;
#pragma unroll
    for (int kh = 0; kh < 4; kh++) {
        int ih = oh * 2 - 1 + kh;
        bool vh = ((unsigned)ih < 112u);
#pragma unroll
        for (int kw = 0; kw < 4; kw++) {
            int iw = ow * 2 - 1 + kw;
            float v = (vh && ((unsigned)iw < 112u)) ? xin[ih * 112 + iw] : 0.f;
            const float4* wp = (const float4*)(ws + (kh * 4 + kw) * 16);
#pragma unroll
            for (int q = 0; q < 4; q++) {
                float4 wv = wp[q];
                acc[4 * q + 0] += v * wv.x;
                acc[4 * q + 1] += v * wv.y;
                acc[4 * q + 2] += v * wv.z;
                acc[4 * q + 3] += v * wv.w;
            }
        }
    }
    float* out = g_y1 + (size_t)n * 16 * 3136;
#pragma unroll
    for (int oc = 0; oc < 16; oc++) out[oc * 3136 + p] = acc[oc];
}

// ---------------- conv2: 16->32, 4x4, stride 2, pad 1, 56 -> 28 ----------------
__global__ __launch_bounds__(416) void conv2_k(const float* __restrict__ w) {
    __shared__ float smi[2 * 58 * 58];  // padded input planes (2 ic at a time)
    __shared__ float smw[2 * 16 * 32];  // [icl][tap][oc]
    const int tid = threadIdx.x;
    const int n = blockIdx.x;

    for (int i = tid; i < 2 * 58 * 58; i += 416) smi[i] = 0.f;

    const int p0 = tid;
    const int p1 = tid + 416;
    const bool v1 = (p1 < 784);
    const int p1c = v1 ? p1 : 783;
    const int oh0 = p0 / 28, ow0 = p0 % 28;
    const int oh1 = p1c / 28, ow1 = p1c % 28;

    float acc0[32], acc1[32];
#pragma unroll
    for (int i = 0; i < 32; i++) { acc0[i] = 0.f; acc1[i] = 0.f; }

    const float* ain = g_y1 + (size_t)n * 16 * 3136;
    __syncthreads();  // zero-fill complete before interior fill

#pragma unroll 1
    for (int ic0 = 0; ic0 < 16; ic0 += 2) {
        for (int i = tid; i < 2 * 3136; i += 416) {
            int icl = i / 3136, r = i % 3136;
            int ih = r / 56, iw = r % 56;
            smi[icl * 3364 + (ih + 1) * 58 + (iw + 1)] = ain[(ic0 + icl) * 3136 + r];
        }
        for (int i = tid; i < 1024; i += 416) {
            int oc = i & 31, t = (i >> 5) & 15, icl = i >> 9;
            smw[i] = w[((oc * 16) + (ic0 + icl)) * 16 + t];
        }
        __syncthreads();
#pragma unroll 1
        for (int icl = 0; icl < 2; icl++) {
            const float* sip = smi + icl * 3364;
#pragma unroll
            for (int t = 0; t < 16; t++) {
                int kh = t >> 2, kw = t & 3;
                float in0 = sip[(oh0 * 2 + kh) * 58 + ow0 * 2 + kw];
                float in1 = sip[(oh1 * 2 + kh) * 58 + ow1 * 2 + kw];
                const float4* wp = (const float4*)(smw + ((icl * 16) + t) * 32);
#pragma unroll
                for (int q = 0; q < 8; q++) {
                    float4 wv = wp[q];
                    acc0[4 * q + 0] += in0 * wv.x; acc1[4 * q + 0] += in1 * wv.x;
                    acc0[4 * q + 1] += in0 * wv.y; acc1[4 * q + 1] += in1 * wv.y;
                    acc0[4 * q + 2] += in0 * wv.z; acc1[4 * q + 2] += in1 * wv.z;
                    acc0[4 * q + 3] += in0 * wv.w; acc1[4 * q + 3] += in1 * wv.w;
                }
            }
        }
        __syncthreads();
    }
    float* out = g_y2 + (size_t)n * 32 * 784;
#pragma unroll
    for (int oc = 0; oc < 32; oc++) {
        out[oc * 784 + p0] = acc0[oc];
        if (v1) out[oc * 784 + p1] = acc1[oc];
    }
}

// ---------------- generic 3x3 s1 p0 conv, 32 OCs per block ----------------
// act/out are REAL device addresses (resolved via cudaGetSymbolAddress on host)
template <int IC, int OC, int IH, int OW, int THREADS>
__global__ __launch_bounds__(THREADS) void conv3x3_k(const float* __restrict__ act,
                                                     const float* __restrict__ w,
                                                     float* __restrict__ out) {
    constexpr int IHW = IH * IH;
    constexpr int PIX = OW * OW;
    __shared__ float smi[8 * IHW];
    __shared__ float smw[8 * 9 * 32];
    const int tid = threadIdx.x;
    const int n = blockIdx.x;
    const int ocb = blockIdx.y;

    const int p0 = tid;
    const int p1 = tid + THREADS;
    const bool v0 = (p0 < PIX);
    const bool v1 = (p1 < PIX);
    const int p0c = v0 ? p0 : (PIX - 1);
    const int p1c = v1 ? p1 : (PIX - 1);
    const int oh0 = p0c / OW, ow0 = p0c % OW;
    const int oh1 = p1c / OW, ow1 = p1c % OW;

    float acc0[32], acc1[32];
#pragma unroll
    for (int i = 0; i < 32; i++) { acc0[i] = 0.f; acc1[i] = 0.f; }

    const float* ain = act + (size_t)n * IC * IHW;

#pragma unroll 1
    for (int ic0 = 0; ic0 < IC; ic0 += 8) {
        for (int i = tid; i < 8 * IHW; i += THREADS) smi[i] = ain[ic0 * IHW + i];
        for (int i = tid; i < 2304; i += THREADS) {
            int oc = i & 31;
            int t = (i >> 5) % 9;
            int icl = i / 288;
            smw[i] = w[(((ocb * 32 + oc) * IC) + ic0 + icl) * 9 + t];
        }
        __syncthreads();
#pragma unroll 1
        for (int icl = 0; icl < 8; icl++) {
            const float* sip = smi + icl * IHW;
#pragma unroll
            for (int t = 0; t < 9; t++) {
                int kh = t / 3, kw = t % 3;
                float in0 = sip[(oh0 + kh) * IH + ow0 + kw];
                float in1 = sip[(oh1 + kh) * IH + ow1 + kw];
                const float4* wp = (const float4*)(smw + (icl * 9 + t) * 32);
#pragma unroll
                for (int q = 0; q < 8; q++) {
                    float4 wv = wp[q];
                    acc0[4 * q + 0] += in0 * wv.x; acc1[4 * q + 0] += in1 * wv.x;
                    acc0[4 * q + 1] += in0 * wv.y; acc1[4 * q + 1] += in1 * wv.y;
                    acc0[4 * q + 2] += in0 * wv.z; acc1[4 * q + 2] += in1 * wv.z;
                    acc0[4 * q + 3] += in0 * wv.w; acc1[4 * q + 3] += in1 * wv.w;
                }
            }
        }
        __syncthreads();
    }

    float* op = out + ((size_t)n * OC + ocb * 32) * PIX;
#pragma unroll
    for (int oc = 0; oc < 32; oc++) {
        if (v0) op[oc * PIX + p0] = acc0[oc];
        if (v1) op[oc * PIX + p1] = acc1[oc];
    }
}

// ---------------- BN stats: per-channel sum / sumsq ----------------
__device__ __forceinline__ void stats_body(const float* __restrict__ y, float* s, float* q,
                                           int C, int HW) {
    __shared__ float rs[256], rq[256];
    int c = blockIdx.x;
    int nb = blockIdx.y;
    float ls = 0.f, lq = 0.f;
    for (int nn = 0; nn < 16; nn++) {
        const float* p = y + ((size_t)(nb * 16 + nn) * C + c) * HW;
        for (int i = threadIdx.x; i < HW; i += 256) {
            float v = p[i];
            ls += v;
            lq += v * v;
        }
    }
    rs[threadIdx.x] = ls;
    rq[threadIdx.x] = lq;
    __syncthreads();
    for (int off = 128; off > 0; off >>= 1) {
        if (threadIdx.x < off) {
            rs[threadIdx.x] += rs[threadIdx.x + off];
            rq[threadIdx.x] += rq[threadIdx.x + off];
        }
        __syncthreads();
    }
    if (threadIdx.x == 0) {
        atomicAdd(&s[c], rs[0]);
        atomicAdd(&q[c], rq[0]);
    }
}
__global__ void stats1_k() { stats_body(g_y1, g_s1, g_q1, 16, 3136); }
__global__ void stats2_k() { stats_body(g_y2, g_s2, g_q2, 32, 784); }
__global__ void stats3_k() { stats_body(g_y3, g_s3, g_q3, 64, 676); }
__global__ void stats4_k() { stats_body(g_y4, g_s4, g_q4, 128, 576); }

// ---------------- BN apply + ReLU (in place) ----------------
__device__ __forceinline__ void bnrelu_body(float* y, const float* s, const float* q,
                                            const float* __restrict__ g,
                                            const float* __restrict__ be, int C, int HW,
                                            float invCnt) {
    int nc = blockIdx.x;
    int c = nc % C;
    float mu = s[c] * invCnt;
    float var = fmaxf(q[c] * invCnt - mu * mu, 0.f);
    float sc = g[c] * rsqrtf(var + 1e-5f);
    float sh = be[c] - mu * sc;
    float* p = y + (size_t)nc * HW;
    for (int i = threadIdx.x; i < HW; i += blockDim.x) p[i] = fmaxf(fmaf(p[i], sc, sh), 0.f);
}
__global__ void bnrelu1_k(const float* g, const float* be) {
    bnrelu_body(g_y1, g_s1, g_q1, g, be, 16, 3136, 1.f / (512.f * 3136.f));
}
__global__ void bnrelu2_k(const float* g, const float* be) {
    bnrelu_body(g_y2, g_s2, g_q2, g, be, 32, 784, 1.f / (512.f * 784.f));
}
__global__ void bnrelu3_k(const float* g, const float* be) {
    bnrelu_body(g_y3, g_s3, g_q3, g, be, 64, 676, 1.f / (512.f * 676.f));
}
__global__ void bnrelu4_k(const float* g, const float* be) {
    bnrelu_body(g_y4, g_s4, g_q4, g, be, 128, 576, 1.f / (512.f * 576.f));
}

// ---------------- global average pool: (512,128,24,24) -> (512,128) ----------------
__global__ void gap_k() {
    int pair = blockIdx.x * 8 + (threadIdx.x >> 5);
    int lane = threadIdx.x & 31;
    const float* p = g_y4 + (size_t)pair * 576;
    float s = 0.f;
    for (int i = lane; i < 576; i += 32) s += p[i];
#pragma unroll
    for (int o = 16; o > 0; o >>= 1) s += __shfl_xor_sync(0xffffffffu, s, o);
    if (lane == 0) g_f[pair] = s * (1.f / 576.f);
}

// ---------------- row-wise L2 normalize (K = 128) ----------------
__global__ void l2norm_body_k(const float* __restrict__ in, float* __restrict__ out, int rows) {
    int r = blockIdx.x * 8 + (threadIdx.x >> 5);
    if (r >= rows) return;
    int lane = threadIdx.x & 31;
    const float* p = in + (size_t)r * 128;
    float v0 = p[lane], v1 = p[lane + 32], v2 = p[lane + 64], v3 = p[lane + 96];
    float sq = v0 * v0 + v1 * v1 + v2 * v2 + v3 * v3;
#pragma unroll
    for (int o = 16; o > 0; o >>= 1) sq += __shfl_xor_sync(0xffffffffu, sq, o);
    float inv = 1.f / fmaxf(sqrtf(sq), 1e-12f);
    float* op = out + (size_t)r * 128;
    op[lane] = v0 * inv;
    op[lane + 32] = v1 * inv;
    op[lane + 64] = v2 * inv;
    op[lane + 96] = v3 * inv;
}

// ---------------- SGEMM: (512 x 128) @ (128 x 100000), x64 scale ----------------
__global__ __launch_bounds__(256) void sgemm_k(const float* __restrict__ A,
                                               const float* __restrict__ B,
                                               float* __restrict__ C) {
    __shared__ float As[8][128];
    __shared__ float Bs[8][128];
    const int tid = threadIdx.x;
    const int bm = blockIdx.y * 128;
    const int bn = blockIdx.x * 128;
    const int tm = (tid >> 4) << 3;
    const int tn = (tid & 15) << 3;

    float acc[8][8];
#pragma unroll
    for (int i = 0; i < 8; i++)
#pragma unroll
        for (int j = 0; j < 8; j++) acc[i][j] = 0.f;

    const int lr = tid >> 1;        // row within 128-tile
    const int lk = (tid & 1) << 2;  // 0 or 4
    const float* Ag = A + (size_t)(bm + lr) * 128 + lk;
    const int brow = bn + lr;
    const float* Bg = B + (size_t)brow * 128 + lk;
    const bool bvalid = (brow < NCLS);

#pragma unroll 1
    for (int k0 = 0; k0 < 128; k0 += 8) {
        float4 av = *(const float4*)(Ag + k0);
        float4 bv = bvalid ? *(const float4*)(Bg + k0) : make_float4(0.f, 0.f, 0.f, 0.f);
        As[lk + 0][lr] = av.x; As[lk + 1][lr] = av.y; As[lk + 2][lr] = av.z; As[lk + 3][lr] = av.w;
        Bs[lk + 0][lr] = bv.x; Bs[lk + 1][lr] = bv.y; Bs[lk + 2][lr] = bv.z; Bs[lk + 3][lr] = bv.w;
        __syncthreads();
#pragma unroll
        for (int kk = 0; kk < 8; kk++) {
            float a[8], b[8];
            *(float4*)(a) = *(const float4*)&As[kk][tm];
            *(float4*)(a + 4) = *(const float4*)&As[kk][tm + 4];
            *(float4*)(b) = *(const float4*)&Bs[kk][tn];
            *(float4*)(b + 4) = *(const float4*)&Bs[kk][tn + 4];
#pragma unroll
            for (int i = 0; i < 8; i++)
#pragma unroll
                for (int j = 0; j < 8; j++) acc[i][j] += a[i] * b[j];
        }
        __syncthreads();
    }

#pragma unroll
    for (int i = 0; i < 8; i++) {
        int m = bm + tm + i;
        float* cp = C + (size_t)m * NCLS + bn + tn;
#pragma unroll
        for (int j = 0; j < 8; j++) {
            if (bn + tn + j < NCLS) cp[j] = 64.f * acc[i][j];
        }
    }
}

// ---------------- ArcFace margin fix-up ----------------
__global__ void margin_k(const int* __restrict__ gt, float* __restrict__ out) {
    int n = blockIdx.x * 256 + threadIdx.x;
    if (n >= NIMG) return;
    int c = gt[n];
    size_t idx = (size_t)n * NCLS + c;
    float v = out[idx] * (1.f / 64.f);
    float s = sqrtf(fmaxf(1.f - v * v, 0.f));
    const float cm = 0.87758256189037271612f;  // cos(0.5)
    const float sm = 0.47942553860420300027f;  // sin(0.5)
    out[idx] = 64.f * (v * cm - s * sm);
}

// ---------------- launch ----------------
extern "C" void kernel_launch(void* const* d_in, const int* in_sizes, int n_in,
                              void* d_out, int out_size) {
    const float* x  = (const float*)d_in[0];
    const int*   gt = (const int*)d_in[1];
    const float* w1 = (const float*)d_in[2];
    const float* g1 = (const float*)d_in[4];
    const float* be1 = (const float*)d_in[5];
    const float* w2 = (const float*)d_in[6];
    const float* g2 = (const float*)d_in[8];
    const float* be2 = (const float*)d_in[9];
    const float* w3 = (const float*)d_in[10];
    const float* g3 = (const float*)d_in[12];
    const float* be3 = (const float*)d_in[13];
    const float* w4 = (const float*)d_in[14];
    const float* g4 = (const float*)d_in[16];
    const float* be4 = (const float*)d_in[17];
    const float* aw = (const float*)d_in[18];
    float* out = (float*)d_out;

    // Resolve REAL device addresses of __device__ globals (host shadow symbols
    // must NOT be passed as kernel args — that was the round-2 bug).
    float *p_y2, *p_y3, *p_y4, *p_f, *p_fn, *p_wn;
    cudaGetSymbolAddress((void**)&p_y2, g_y2);
    cudaGetSymbolAddress((void**)&p_y3, g_y3);
    cudaGetSymbolAddress((void**)&p_y4, g_y4);
    cudaGetSymbolAddress((void**)&p_f, g_f);
    cudaGetSymbolAddress((void**)&p_fn, g_fn);
    cudaGetSymbolAddress((void**)&p_wn, g_wn);

    zero_stats_k<<<1, 128>>>();

    // layer 1
    conv1_k<<<dim3(512, 13), 256>>>(x, w1);
    stats1_k<<<dim3(16, 32), 256>>>();
    bnrelu1_k<<<512 * 16, 256>>>(g1, be1);

    // layer 2
    conv2_k<<<512, 416>>>(w2);
    stats2_k<<<dim3(32, 32), 256>>>();
    bnrelu2_k<<<512 * 32, 256>>>(g2, be2);

    // layer 3 (32->64, 28->26)
    conv3x3_k<32, 64, 28, 26, 352><<<dim3(512, 2), 352>>>(p_y2, w3, p_y3);
    stats3_k<<<dim3(64, 32), 256>>>();
    bnrelu3_k<<<512 * 64, 256>>>(g3, be3);

    // layer 4 (64->128, 26->24)
    conv3x3_k<64, 128, 26, 24, 288><<<dim3(512, 4), 288>>>(p_y3, w4, p_y4);
    stats4_k<<<dim3(128, 32), 256>>>();
    bnrelu4_k<<<512 * 128, 256>>>(g4, be4);

    // pool + normalize
    gap_k<<<512 * 128 / 8, 256>>>();
    l2norm_body_k<<<64, 256>>>(p_f, p_fn, 512);
    l2norm_body_k<<<(NCLS + 7) / 8, 256>>>(aw, p_wn, NCLS);

    // cosine logits (x64) + margin
    sgemm_k<<<dim3((NCLS + 127) / 128, 4), 256>>>(p_fn, p_wn, out);
    margin_k<<<2, 256>>>(gt, out);
}

// round 8
// speedup vs baseline: 1.0736x; 1.0736x over previous
#include <cuda_runtime.h>
#include <math.h>

#define NIMG 512
#define NCLS 100000

// ---------------- scratch (device globals; no allocation) ----------------
__device__ float g_y1[512 * 16 * 56 * 56];   // conv1 raw out
__device__ float g_y2[512 * 32 * 28 * 28];   // conv2 raw out
__device__ float g_y3[512 * 64 * 26 * 26];   // conv3 raw out
__device__ float g_y4[512 * 128 * 24 * 24];  // conv4 raw out
__device__ float g_f[512 * 128];
__device__ float g_fn[512 * 128];
__device__ float g_wn[NCLS * 128];
__device__ float g_s1[16], g_q1[16], g_sc1[16], g_sh1[16];
__device__ float g_s2[32], g_q2[32], g_sc2[32], g_sh2[32];
__device__ float g_s3[64], g_q3[64], g_sc3[64], g_sh3[64];
__device__ float g_s4[128], g_q4[128], g_sc4[128], g_sh4[128];

__global__ void zero_stats_k() {
    int t = threadIdx.x;
    if (t < 16)  { g_s1[t] = 0.f; g_q1[t] = 0.f; }
    if (t < 32)  { g_s2[t] = 0.f; g_q2[t] = 0.f; }
    if (t < 64)  { g_s3[t] = 0.f; g_q3[t] = 0.f; }
    if (t < 128) { g_s4[t] = 0.f; g_q4[t] = 0.f; }
}

// stats -> (scale, shift)
__global__ void scale_k(const float* __restrict__ s, const float* __restrict__ q,
                        const float* __restrict__ g, const float* __restrict__ be,
                        float* __restrict__ sc, float* __restrict__ sh, int C, float invCnt) {
    int c = threadIdx.x;
    if (c >= C) return;
    float mu = s[c] * invCnt;
    float var = fmaxf(q[c] * invCnt - mu * mu, 0.f);
    float a = g[c] * rsqrtf(var + 1e-5f);
    sc[c] = a;
    sh[c] = be[c] - mu * a;
}

// ---------------- conv1: 1->16, 4x4, s2, p1, 112 -> 56 (+fused stats) ----------------
__global__ __launch_bounds__(256) void conv1_k(const float* __restrict__ x,
                                               const float* __restrict__ w) {
    __shared__ float ws[256];  // [tap][oc]
    __shared__ float bs[16], bq[16];
    int tid = threadIdx.x;
    ws[(tid & 15) * 16 + (tid >> 4)] = w[tid];
    if (tid < 16) { bs[tid] = 0.f; bq[tid] = 0.f; }
    __syncthreads();
    int n = blockIdx.x;
    int p = blockIdx.y * 256 + tid;
    bool valid = (p < 3136);
    int pc = valid ? p : 3135;
    int oh = pc / 56, ow = pc % 56;
    const float* xin = x + (size_t)n * 112 * 112;
    float acc[16];
#pragma unroll
    for (int i = 0; i < 16; i++) acc[i] = 0.f;
#pragma unroll
    for (int kh = 0; kh < 4; kh++) {
        int ih = oh * 2 - 1 + kh;
        bool vh = ((unsigned)ih < 112u);
#pragma unroll
        for (int kw = 0; kw < 4; kw++) {
            int iw = ow * 2 - 1 + kw;
            float v = (vh && ((unsigned)iw < 112u)) ? xin[ih * 112 + iw] : 0.f;
            const float4* wp = (const float4*)(ws + (kh * 4 + kw) * 16);
#pragma unroll
            for (int q = 0; q < 4; q++) {
                float4 wv = wp[q];
                acc[4 * q + 0] += v * wv.x;
                acc[4 * q + 1] += v * wv.y;
                acc[4 * q + 2] += v * wv.z;
                acc[4 * q + 3] += v * wv.w;
            }
        }
    }
    float* out = g_y1 + (size_t)n * 16 * 3136;
    if (valid) {
#pragma unroll
        for (int oc = 0; oc < 16; oc++) out[oc * 3136 + p] = acc[oc];
    }
    // fused per-channel stats
    int lane = tid & 31;
#pragma unroll
    for (int oc = 0; oc < 16; oc++) {
        float v = valid ? acc[oc] : 0.f;
        float q = v * v;
#pragma unroll
        for (int o = 16; o > 0; o >>= 1) {
            v += __shfl_xor_sync(0xffffffffu, v, o);
            q += __shfl_xor_sync(0xffffffffu, q, o);
        }
        if (lane == 0) { atomicAdd(&bs[oc], v); atomicAdd(&bq[oc], q); }
    }
    __syncthreads();
    if (tid < 16) { atomicAdd(&g_s1[tid], bs[tid]); atomicAdd(&g_q1[tid], bq[tid]); }
}

// ---------------- conv2: 16->32, 4x4, s2, p1, 56 -> 28 (bn1+relu fused in, stats out) ----------------
__global__ __launch_bounds__(416) void conv2_k(const float* __restrict__ w) {
    __shared__ float smi[2 * 58 * 58];
    __shared__ float smw[2 * 16 * 32];
    __shared__ float bs[32], bq[32];
    const int tid = threadIdx.x;
    const int n = blockIdx.x;

    for (int i = tid; i < 2 * 58 * 58; i += 416) smi[i] = 0.f;
    if (tid < 32) { bs[tid] = 0.f; bq[tid] = 0.f; }

    const int p0 = tid;
    const int p1 = tid + 416;
    const bool v1 = (p1 < 784);
    const int p1c = v1 ? p1 : 783;
    const int oh0 = p0 / 28, ow0 = p0 % 28;
    const int oh1 = p1c / 28, ow1 = p1c % 28;

    float acc0[32], acc1[32];
#pragma unroll
    for (int i = 0; i < 32; i++) { acc0[i] = 0.f; acc1[i] = 0.f; }

    const float* ain = g_y1 + (size_t)n * 16 * 3136;
    __syncthreads();

#pragma unroll 1
    for (int ic0 = 0; ic0 < 16; ic0 += 2) {
        float scA = g_sc1[ic0], shA = g_sh1[ic0];
        float scB = g_sc1[ic0 + 1], shB = g_sh1[ic0 + 1];
        for (int i = tid; i < 2 * 3136; i += 416) {
            int icl = i / 3136, r = i % 3136;
            int ih = r / 56, iw = r % 56;
            float raw = ain[(ic0 + icl) * 3136 + r];
            float sc = icl ? scB : scA, sh = icl ? shB : shA;
            smi[icl * 3364 + (ih + 1) * 58 + (iw + 1)] = fmaxf(fmaf(raw, sc, sh), 0.f);
        }
        for (int i = tid; i < 1024; i += 416) {
            int oc = i & 31, t = (i >> 5) & 15, icl = i >> 9;
            smw[i] = w[((oc * 16) + (ic0 + icl)) * 16 + t];
        }
        __syncthreads();
#pragma unroll 1
        for (int icl = 0; icl < 2; icl++) {
            const float* sip = smi + icl * 3364;
#pragma unroll
            for (int t = 0; t < 16; t++) {
                int kh = t >> 2, kw = t & 3;
                float in0 = sip[(oh0 * 2 + kh) * 58 + ow0 * 2 + kw];
                float in1 = sip[(oh1 * 2 + kh) * 58 + ow1 * 2 + kw];
                const float4* wp = (const float4*)(smw + ((icl * 16) + t) * 32);
#pragma unroll
                for (int q = 0; q < 8; q++) {
                    float4 wv = wp[q];
                    acc0[4 * q + 0] += in0 * wv.x; acc1[4 * q + 0] += in1 * wv.x;
                    acc0[4 * q + 1] += in0 * wv.y; acc1[4 * q + 1] += in1 * wv.y;
                    acc0[4 * q + 2] += in0 * wv.z; acc1[4 * q + 2] += in1 * wv.z;
                    acc0[4 * q + 3] += in0 * wv.w; acc1[4 * q + 3] += in1 * wv.w;
                }
            }
        }
        __syncthreads();
    }
    float* out = g_y2 + (size_t)n * 32 * 784;
#pragma unroll
    for (int oc = 0; oc < 32; oc++) {
        out[oc * 784 + p0] = acc0[oc];
        if (v1) out[oc * 784 + p1] = acc1[oc];
    }
    int lane = tid & 31;
#pragma unroll
    for (int oc = 0; oc < 32; oc++) {
        float v = acc0[oc] + (v1 ? acc1[oc] : 0.f);
        float q = acc0[oc] * acc0[oc] + (v1 ? acc1[oc] * acc1[oc] : 0.f);
#pragma unroll
        for (int o = 16; o > 0; o >>= 1) {
            v += __shfl_xor_sync(0xffffffffu, v, o);
            q += __shfl_xor_sync(0xffffffffu, q, o);
        }
        if (lane == 0) { atomicAdd(&bs[oc], v); atomicAdd(&bq[oc], q); }
    }
    __syncthreads();
    if (tid < 32) { atomicAdd(&g_s2[tid], bs[tid]); atomicAdd(&g_q2[tid], bq[tid]); }
}

// ---------------- generic 3x3 s1 p0 conv, 32 OCs/block, bn+relu fused in, stats out ---------
template <int IC, int OC, int IH, int OW, int THREADS>
__global__ __launch_bounds__(THREADS) void conv3x3_k(
    const float* __restrict__ act, const float* __restrict__ w, float* __restrict__ out,
    const float* __restrict__ isc, const float* __restrict__ ish,
    float* __restrict__ gs, float* __restrict__ gq) {
    constexpr int IHW = IH * IH;
    constexpr int PIX = OW * OW;
    __shared__ float smi[8 * IHW];
    __shared__ float smw[8 * 9 * 32];
    __shared__ float bs[32], bq[32];
    const int tid = threadIdx.x;
    const int n = blockIdx.x;
    const int ocb = blockIdx.y;

    if (tid < 32) { bs[tid] = 0.f; bq[tid] = 0.f; }

    const int p0 = tid;
    const int p1 = tid + THREADS;
    const bool v0 = (p0 < PIX);
    const bool v1 = (p1 < PIX);
    const int p0c = v0 ? p0 : (PIX - 1);
    const int p1c = v1 ? p1 : (PIX - 1);
    const int oh0 = p0c / OW, ow0 = p0c % OW;
    const int oh1 = p1c / OW, ow1 = p1c % OW;

    float acc0[32], acc1[32];
#pragma unroll
    for (int i = 0; i < 32; i++) { acc0[i] = 0.f; acc1[i] = 0.f; }

    const float* ain = act + (size_t)n * IC * IHW;

#pragma unroll 1
    for (int ic0 = 0; ic0 < IC; ic0 += 8) {
        for (int i = tid; i < 8 * IHW; i += THREADS) {
            int c = ic0 + i / IHW;
            smi[i] = fmaxf(fmaf(ain[ic0 * IHW + i], __ldg(&isc[c]), __ldg(&ish[c])), 0.f);
        }
        for (int i = tid; i < 2304; i += THREADS) {
            int oc = i & 31;
            int t = (i >> 5) % 9;
            int icl = i / 288;
            smw[i] = w[(((ocb * 32 + oc) * IC) + ic0 + icl) * 9 + t];
        }
        __syncthreads();
#pragma unroll 1
        for (int icl = 0; icl < 8; icl++) {
            const float* sip = smi + icl * IHW;
#pragma unroll
            for (int t = 0; t < 9; t++) {
                int kh = t / 3, kw = t % 3;
                float in0 = sip[(oh0 + kh) * IH + ow0 + kw];
                float in1 = sip[(oh1 + kh) * IH + ow1 + kw];
                const float4* wp = (const float4*)(smw + (icl * 9 + t) * 32);
#pragma unroll
                for (int q = 0; q < 8; q++) {
                    float4 wv = wp[q];
                    acc0[4 * q + 0] += in0 * wv.x; acc1[4 * q + 0] += in1 * wv.x;
                    acc0[4 * q + 1] += in0 * wv.y; acc1[4 * q + 1] += in1 * wv.y;
                    acc0[4 * q + 2] += in0 * wv.z; acc1[4 * q + 2] += in1 * wv.z;
                    acc0[4 * q + 3] += in0 * wv.w; acc1[4 * q + 3] += in1 * wv.w;
                }
            }
        }
        __syncthreads();
    }

    float* op = out + ((size_t)n * OC + ocb * 32) * PIX;
#pragma unroll
    for (int oc = 0; oc < 32; oc++) {
        if (v0) op[oc * PIX + p0] = acc0[oc];
        if (v1) op[oc * PIX + p1] = acc1[oc];
    }
    int lane = tid & 31;
#pragma unroll
    for (int oc = 0; oc < 32; oc++) {
        float a0 = v0 ? acc0[oc] : 0.f;
        float a1 = v1 ? acc1[oc] : 0.f;
        float v = a0 + a1;
        float q = a0 * a0 + a1 * a1;
#pragma unroll
        for (int o = 16; o > 0; o >>= 1) {
            v += __shfl_xor_sync(0xffffffffu, v, o);
            q += __shfl_xor_sync(0xffffffffu, q, o);
        }
        if (lane == 0) { atomicAdd(&bs[oc], v); atomicAdd(&bq[oc], q); }
    }
    __syncthreads();
    if (tid < 32) {
        atomicAdd(&gs[ocb * 32 + tid], bs[tid]);
        atomicAdd(&gq[ocb * 32 + tid], bq[tid]);
    }
}

// ---------------- GAP with bn4+relu fused: (512,128,24,24) -> (512,128) ----------------
__global__ void gap_k() {
    int pair = blockIdx.x * 8 + (threadIdx.x >> 5);
    int c = pair & 127;
    int lane = threadIdx.x & 31;
    float sc = g_sc4[c], sh = g_sh4[c];
    const float* p = g_y4 + (size_t)pair * 576;
    float s = 0.f;
    for (int i = lane; i < 576; i += 32) s += fmaxf(fmaf(p[i], sc, sh), 0.f);
#pragma unroll
    for (int o = 16; o > 0; o >>= 1) s += __shfl_xor_sync(0xffffffffu, s, o);
    if (lane == 0) g_f[pair] = s * (1.f / 576.f);
}

// ---------------- row-wise L2 normalize (K = 128) ----------------
__global__ void l2norm_body_k(const float* __restrict__ in, float* __restrict__ out, int rows) {
    int r = blockIdx.x * 8 + (threadIdx.x >> 5);
    if (r >= rows) return;
    int lane = threadIdx.x & 31;
    const float* p = in + (size_t)r * 128;
    float v0 = p[lane], v1 = p[lane + 32], v2 = p[lane + 64], v3 = p[lane + 96];
    float sq = v0 * v0 + v1 * v1 + v2 * v2 + v3 * v3;
#pragma unroll
    for (int o = 16; o > 0; o >>= 1) sq += __shfl_xor_sync(0xffffffffu, sq, o);
    float inv = 1.f / fmaxf(sqrtf(sq), 1e-12f);
    float* op = out + (size_t)r * 128;
    op[lane] = v0 * inv;
    op[lane + 32] = v1 * inv;
    op[lane + 64] = v2 * inv;
    op[lane + 96] = v3 * inv;
}

// ---------------- SGEMM: (512 x 128) @ (128 x 100000)^T, x64 scale ----------------
__global__ __launch_bounds__(256) void sgemm_k(const float* __restrict__ A,
                                               const float* __restrict__ B,
                                               float* __restrict__ C) {
    __shared__ float As[8][128];
    __shared__ float Bs[8][128];
    const int tid = threadIdx.x;
    const int bm = blockIdx.y * 128;
    const int bn = blockIdx.x * 128;
    const int tm = (tid >> 4) << 3;
    const int tn = (tid & 15) << 3;

    float acc[8][8];
#pragma unroll
    for (int i = 0; i < 8; i++)
#pragma unroll
        for (int j = 0; j < 8; j++) acc[i][j] = 0.f;

    const int lr = tid >> 1;
    const int lk = (tid & 1) << 2;
    const float* Ag = A + (size_t)(bm + lr) * 128 + lk;
    const int brow = bn + lr;
    const float* Bg = B + (size_t)brow * 128 + lk;
    const bool bvalid = (brow < NCLS);

#pragma unroll 1
    for (int k0 = 0; k0 < 128; k0 += 8) {
        float4 av = *(const float4*)(Ag + k0);
        float4 bv = bvalid ? *(const float4*)(Bg + k0) : make_float4(0.f, 0.f, 0.f, 0.f);
        As[lk + 0][lr] = av.x; As[lk + 1][lr] = av.y; As[lk + 2][lr] = av.z; As[lk + 3][lr] = av.w;
        Bs[lk + 0][lr] = bv.x; Bs[lk + 1][lr] = bv.y; Bs[lk + 2][lr] = bv.z; Bs[lk + 3][lr] = bv.w;
        __syncthreads();
#pragma unroll
        for (int kk = 0; kk < 8; kk++) {
            float a[8], b[8];
            *(float4*)(a) = *(const float4*)&As[kk][tm];
            *(float4*)(a + 4) = *(const float4*)&As[kk][tm + 4];
            *(float4*)(b) = *(const float4*)&Bs[kk][tn];
            *(float4*)(b + 4) = *(const float4*)&Bs[kk][tn + 4];
#pragma unroll
            for (int i = 0; i < 8; i++)
#pragma unroll
                for (int j = 0; j < 8; j++) acc[i][j] += a[i] * b[j];
        }
        __syncthreads();
    }

    const bool full = (bn + 128 <= NCLS);
#pragma unroll
    for (int i = 0; i < 8; i++) {
        float* cp = C + (size_t)(bm + tm + i) * NCLS + bn + tn;
        if (full) {
            float4 o0 = make_float4(64.f * acc[i][0], 64.f * acc[i][1],
                                    64.f * acc[i][2], 64.f * acc[i][3]);
            float4 o1 = make_float4(64.f * acc[i][4], 64.f * acc[i][5],
                                    64.f * acc[i][6], 64.f * acc[i][7]);
            *(float4*)cp = o0;
            *(float4*)(cp + 4) = o1;
        } else {
#pragma unroll
            for (int j = 0; j < 8; j++)
                if (bn + tn + j < NCLS) cp[j] = 64.f * acc[i][j];
        }
    }
}

// ---------------- ArcFace margin fix-up ----------------
__global__ void margin_k(const int* __restrict__ gt, float* __restrict__ out) {
    int n = blockIdx.x * 256 + threadIdx.x;
    if (n >= NIMG) return;
    int c = gt[n];
    size_t idx = (size_t)n * NCLS + c;
    float v = out[idx] * (1.f / 64.f);
    float s = sqrtf(fmaxf(1.f - v * v, 0.f));
    const float cm = 0.87758256189037271612f;  // cos(0.5)
    const float sm = 0.47942553860420300027f;  // sin(0.5)
    out[idx] = 64.f * (v * cm - s * sm);
}

// ---------------- launch ----------------
extern "C" void kernel_launch(void* const* d_in, const int* in_sizes, int n_in,
                              void* d_out, int out_size) {
    const float* x  = (const float*)d_in[0];
    const int*   gt = (const int*)d_in[1];
    const float* w1 = (const float*)d_in[2];
    const float* g1 = (const float*)d_in[4];
    const float* be1 = (const float*)d_in[5];
    const float* w2 = (const float*)d_in[6];
    const float* g2 = (const float*)d_in[8];
    const float* be2 = (const float*)d_in[9];
    const float* w3 = (const float*)d_in[10];
    const float* g3 = (const float*)d_in[12];
    const float* be3 = (const float*)d_in[13];
    const float* w4 = (const float*)d_in[14];
    const float* g4 = (const float*)d_in[16];
    const float* be4 = (const float*)d_in[17];
    const float* aw = (const float*)d_in[18];
    float* out = (float*)d_out;

    // Resolve REAL device addresses of __device__ globals (host shadows are not device ptrs).
    float *p_y2, *p_y3, *p_y4, *p_f, *p_fn, *p_wn;
    float *p_s1, *p_q1, *p_sc1, *p_sh1;
    float *p_s2, *p_q2, *p_sc2, *p_sh2;
    float *p_s3, *p_q3, *p_sc3, *p_sh3;
    float *p_s4, *p_q4, *p_sc4, *p_sh4;
    cudaGetSymbolAddress((void**)&p_y2, g_y2);
    cudaGetSymbolAddress((void**)&p_y3, g_y3);
    cudaGetSymbolAddress((void**)&p_y4, g_y4);
    cudaGetSymbolAddress((void**)&p_f, g_f);
    cudaGetSymbolAddress((void**)&p_fn, g_fn);
    cudaGetSymbolAddress((void**)&p_wn, g_wn);
    cudaGetSymbolAddress((void**)&p_s1, g_s1);   cudaGetSymbolAddress((void**)&p_q1, g_q1);
    cudaGetSymbolAddress((void**)&p_sc1, g_sc1); cudaGetSymbolAddress((void**)&p_sh1, g_sh1);
    cudaGetSymbolAddress((void**)&p_s2, g_s2);   cudaGetSymbolAddress((void**)&p_q2, g_q2);
    cudaGetSymbolAddress((void**)&p_sc2, g_sc2); cudaGetSymbolAddress((void**)&p_sh2, g_sh2);
    cudaGetSymbolAddress((void**)&p_s3, g_s3);   cudaGetSymbolAddress((void**)&p_q3, g_q3);
    cudaGetSymbolAddress((void**)&p_sc3, g_sc3); cudaGetSymbolAddress((void**)&p_sh3, g_sh3);
    cudaGetSymbolAddress((void**)&p_s4, g_s4);   cudaGetSymbolAddress((void**)&p_q4, g_q4);
    cudaGetSymbolAddress((void**)&p_sc4, g_sc4); cudaGetSymbolAddress((void**)&p_sh4, g_sh4);

    zero_stats_k<<<1, 128>>>();

    // layer 1: conv (+stats) -> scale
    conv1_k<<<dim3(512, 13), 256>>>(x, w1);
    scale_k<<<1, 16>>>(p_s1, p_q1, g1, be1, p_sc1, p_sh1, 16, 1.f / (512.f * 3136.f));

    // layer 2: conv (bn1 fused in, +stats) -> scale
    conv2_k<<<512, 416>>>(w2);
    scale_k<<<1, 32>>>(p_s2, p_q2, g2, be2, p_sc2, p_sh2, 32, 1.f / (512.f * 784.f));

    // layer 3: 32->64, 28->26
    conv3x3_k<32, 64, 28, 26, 352><<<dim3(512, 2), 352>>>(p_y2, w3, p_y3, p_sc2, p_sh2, p_s3, p_q3);
    scale_k<<<1, 64>>>(p_s3, p_q3, g3, be3, p_sc3, p_sh3, 64, 1.f / (512.f * 676.f));

    // layer 4: 64->128, 26->24
    conv3x3_k<64, 128, 26, 24, 288><<<dim3(512, 4), 288>>>(p_y3, w4, p_y4, p_sc3, p_sh3, p_s4, p_q4);
    scale_k<<<1, 128>>>(p_s4, p_q4, g4, be4, p_sc4, p_sh4, 128, 1.f / (512.f * 576.f));

    // pool (bn4 fused) + normalize
    gap_k<<<512 * 128 / 8, 256>>>();
    l2norm_body_k<<<64, 256>>>(p_f, p_fn, 512);
    l2norm_body_k<<<(NCLS + 7) / 8, 256>>>(aw, p_wn, NCLS);

    // cosine logits (x64) + margin
    sgemm_k<<<dim3((NCLS + 127) / 128, 4), 256>>>(p_fn, p_wn, out);
    margin_k<<<2, 256>>>(gt, out);
}